// round 10
// baseline (speedup 1.0000x reference)
#include <cuda_runtime.h>
#include <cstdint>

#define HDIM 1024
#define NCTA 128
#define NTHR 512

// Persistent cross-kernel state (allocation-free: __device__ globals).
__device__ unsigned g_counter;          // grid arrive counter (monotonic within a launch)
__device__ float g_hbuf[2][HDIM];       // double-buffered hidden state

__global__ void lstm_init_kernel() { g_counter = 0u; }

__device__ __forceinline__ unsigned ld_acquire_gpu(const unsigned* p) {
    unsigned v;
    asm volatile("ld.acquire.gpu.global.u32 %0, [%1];" : "=r"(v) : "l"(p) : "memory");
    return v;
}
__device__ __forceinline__ void red_release_gpu_add(unsigned* p, unsigned v) {
    asm volatile("red.release.gpu.global.add.u32 [%0], %1;" :: "l"(p), "r"(v) : "memory");
}
__device__ __forceinline__ float4 ldcg_f4(const float4* p) {
    float4 v;
    asm volatile("ld.global.cg.v4.f32 {%0,%1,%2,%3}, [%4];"
                 : "=f"(v.x), "=f"(v.y), "=f"(v.z), "=f"(v.w) : "l"(p) : "memory");
    return v;
}
// Packed fp32x2 FMA (Blackwell): d.lo += a.lo*b.lo, d.hi += a.hi*b.hi (full fp32)
__device__ __forceinline__ void fma2(unsigned long long& d, unsigned long long a, unsigned long long b) {
    asm volatile("fma.rn.f32x2 %0, %1, %2, %0;" : "+l"(d) : "l"(a), "l"(b));
}
__device__ __forceinline__ float2 unpack2(unsigned long long v) {
    float2 r;
    asm("mov.b64 {%0, %1}, %2;" : "=f"(r.x), "=f"(r.y) : "l"(v));
    return r;
}

// 128 CTAs x 512 threads. CTA b owns hidden units [8b, 8b+8) => 32 gate rows
// (local row r = gate*8 + jj, global row R = (r>>3)*1024 + b*8 + (r&7)).
// Warp pair p = w>>1 owns local rows {4p..4p+3}; ch = w&1 selects the column
// half [512*ch, 512*ch+512). Each lane holds 4 rows x 16 cols of W_hh in
// registers. Pair partials combine through psum[] in shared memory; warp 0
// evaluates gates. Sync: single global counter, red.release arrive; warp 15
// is the sole poller AND the h fetcher (poll + 8x LDG.128/lane + STS), so
// detect->fetch happens in one running warp and one barrier replaces two.
__global__ void __launch_bounds__(NTHR, 1)
lstm_kernel(const float* __restrict__ x,
            const float* __restrict__ W_ih,
            const float* __restrict__ W_hh,
            const float* __restrict__ b_ih,
            const float* __restrict__ b_hh,
            const int*   __restrict__ nn,
            float*       __restrict__ out)
{
    __shared__ float hsm[HDIM];
    __shared__ float psum[64];     // [warp*4 + rowslot]

    const int tid = threadIdx.x;
    const int w   = tid >> 5;
    const int l   = tid & 31;
    const int b   = blockIdx.x;
    const int N   = *nn;

    const int p   = w >> 1;
    const int ch  = w & 1;
    const int kb  = ch * 512 + l * 4;      // base column for this lane

    int R[4];
    #pragma unroll
    for (int j = 0; j < 4; j++) {
        int r = 4 * p + j;
        R[j] = (r >> 3) * HDIM + b * 8 + (r & 7);
    }

    // Stage x into hsm (reused for h each step).
    *(float2*)(hsm + 2 * tid) = *(const float2*)(x + 2 * tid);

    // Pin W_hh weights in registers: wt[j][c] covers row R[j], cols kb+c*128..+3.
    ulonglong2 wt[4][4];
    #pragma unroll
    for (int j = 0; j < 4; j++) {
        const char* base = (const char*)(W_hh + (size_t)R[j] * HDIM + kb);
        #pragma unroll
        for (int c = 0; c < 4; c++)
            wt[j][c] = __ldg((const ulonglong2*)(base + c * 512));
    }
    __syncthreads();   // x staged

    // x-gate partials over this warp's column half (+ biases on even warp only).
    float xg[4];
    {
        unsigned long long a0[4] = {0,0,0,0}, a1[4] = {0,0,0,0};
        #pragma unroll
        for (int c = 0; c < 4; c++) {
            ulonglong2 hv = *(const ulonglong2*)(hsm + kb + c * 128);
            #pragma unroll
            for (int j = 0; j < 4; j++) {
                ulonglong2 wv = __ldg((const ulonglong2*)
                    ((const char*)(W_ih + (size_t)R[j] * HDIM + kb) + c * 512));
                fma2(a0[j], wv.x, hv.x);
                fma2(a1[j], wv.y, hv.y);
            }
        }
        #pragma unroll
        for (int j = 0; j < 4; j++) {
            float2 u0 = unpack2(a0[j]), u1 = unpack2(a1[j]);
            xg[j] = (u0.x + u0.y) + (u1.x + u1.y);
        }
        #pragma unroll
        for (int off = 16; off; off >>= 1) {
            #pragma unroll
            for (int j = 0; j < 4; j++)
                xg[j] += __shfl_xor_sync(0xffffffffu, xg[j], off);
        }
        if (ch == 0) {
            #pragma unroll
            for (int j = 0; j < 4; j++)
                xg[j] += b_ih[R[j]] + b_hh[R[j]];
        }
    }

    float cstate = 0.f;   // cell state: warp 0 lanes 0..7

    // ---- step 0: h = 0 -> gates = x_gates ----
    if (l == 0) {
        #pragma unroll
        for (int j = 0; j < 4; j++) psum[w * 4 + j] = xg[j];
    }
    __syncthreads();
    if (w == 0) {
        float gv = psum[8 * (l >> 2) + (l & 3)] + psum[8 * (l >> 2) + (l & 3) + 4];
        const bool isG = (l >= 16) && (l < 24);
        float e = __expf(isG ? -2.0f * gv : -gv);
        float rr = __fdividef(1.0f, 1.0f + e);
        float v = isG ? fmaf(2.0f, rr, -1.0f) : rr;
        float fg = __shfl_sync(0xffffffffu, v, (l + 8)  & 31);
        float gg = __shfl_sync(0xffffffffu, v, (l + 16) & 31);
        float og = __shfl_sync(0xffffffffu, v, (l + 24) & 31);
        float h = 0.f;
        if (l < 8) {
            float c = fmaf(fg, cstate, v * gg);
            cstate  = c;
            float e2 = __expf(-2.0f * c);
            h = og * fmaf(2.0f, __fdividef(1.0f, 1.0f + e2), -1.0f);
            g_hbuf[1][b * 8 + l] = h;      // h_1 -> buf[1]
        }
        __syncwarp();
        if (l == 0) red_release_gpu_add(&g_counter, 1u);
        if (l < 8) out[b * 8 + l] = h;     // out row 0 = h_1 (off critical path)
    }

    // ---- steps 1..N-1 ----
    for (int s = 1; s < N; s++) {
        // Warp 15: sole poller (32 lanes on one address -> 1 coalesced L2
        // request) AND fetcher of the full 4KB h_s (8x LDG.128/lane, MLP=8).
        // Safe to overwrite hsm before the barrier: counter>=target implies
        // this CTA's warp 0 published h_s, which (via barrier C + RED release
        // chain) implies all local matvec reads of hsm for step s-1 are done.
        if (w == 15) {
            const unsigned target = (unsigned)NCTA * (unsigned)s;
            while (ld_acquire_gpu(&g_counter) < target) { }
            const float4* src = (const float4*)&g_hbuf[s & 1][0];
            #pragma unroll
            for (int i = 0; i < 8; i++) {
                float4 hv = ldcg_f4(src + i * 32 + l);
                *(float4*)(hsm + 4 * (i * 32 + l)) = hv;
            }
        }
        __syncthreads();   // (AB) hsm ready; fences psum reuse

        // Matvec over this warp's column half: 4 rows, packed fp32x2 FMA.
        unsigned long long a0[4] = {0,0,0,0}, a1[4] = {0,0,0,0};
        #pragma unroll
        for (int c = 0; c < 4; c++) {
            ulonglong2 hv = *(const ulonglong2*)(hsm + kb + c * 128);
            #pragma unroll
            for (int j = 0; j < 4; j++) {
                fma2(a0[j], wt[j][c].x, hv.x);
                fma2(a1[j], wt[j][c].y, hv.y);
            }
        }
        float pv[4];
        #pragma unroll
        for (int j = 0; j < 4; j++) {
            float2 u0 = unpack2(a0[j]), u1 = unpack2(a1[j]);
            pv[j] = (u0.x + u0.y) + (u1.x + u1.y);
        }
        #pragma unroll
        for (int off = 16; off; off >>= 1) {
            #pragma unroll
            for (int j = 0; j < 4; j++)
                pv[j] += __shfl_xor_sync(0xffffffffu, pv[j], off);
        }
        if (l == 0) {
            #pragma unroll
            for (int j = 0; j < 4; j++) psum[w * 4 + j] = pv[j] + xg[j];
        }
        __syncthreads();   // (C) psums ready

        // Warp 0: combine pair partials, gates, state update, publish.
        if (w == 0) {
            float gv = psum[8 * (l >> 2) + (l & 3)] + psum[8 * (l >> 2) + (l & 3) + 4];
            const bool isG = (l >= 16) && (l < 24);
            float e = __expf(isG ? -2.0f * gv : -gv);
            float rr = __fdividef(1.0f, 1.0f + e);
            float v = isG ? fmaf(2.0f, rr, -1.0f) : rr;
            float fg = __shfl_sync(0xffffffffu, v, (l + 8)  & 31);
            float gg = __shfl_sync(0xffffffffu, v, (l + 16) & 31);
            float og = __shfl_sync(0xffffffffu, v, (l + 24) & 31);
            float h = 0.f;
            if (l < 8) {
                float c = fmaf(fg, cstate, v * gg);
                cstate  = c;
                float e2 = __expf(-2.0f * c);
                h = og * fmaf(2.0f, __fdividef(1.0f, 1.0f + e2), -1.0f);
                g_hbuf[(s + 1) & 1][b * 8 + l] = h;    // publish FIRST
            }
            __syncwarp();
            if (l == 0) red_release_gpu_add(&g_counter, 1u);
            if (l < 8) out[(size_t)s * HDIM + b * 8 + l] = h;  // out row s = h_{s+1}
        }
        // Warps 1..14 run straight to barrier AB of step s+1 and park; warp 15
        // polls while warp 0 finishes gates (different SMSPs). Barrier AB of
        // the next iteration orders psum reuse behind warp 0's reads.
    }
}

extern "C" void kernel_launch(void* const* d_in, const int* in_sizes, int n_in,
                              void* d_out, int out_size) {
    const float* x    = (const float*)d_in[0];   // projected_representation [1,1024]
    const float* Wih  = (const float*)d_in[1];   // [4096,1024]
    const float* Whh  = (const float*)d_in[2];   // [4096,1024]
    const float* bih  = (const float*)d_in[3];   // [4096]
    const float* bhh  = (const float*)d_in[4];   // [4096]
    const int*   nn   = (const int*)d_in[5];     // num_nodes
    float* out = (float*)d_out;                  // [N,1024] fp32

    lstm_init_kernel<<<1, 1>>>();
    lstm_kernel<<<NCTA, NTHR>>>(x, Wih, Whh, bih, bhh, nn, out);
}